// round 17
// baseline (speedup 1.0000x reference)
#include <cuda_runtime.h>
#include <cuda_bf16.h>
#include <cstdint>

#define H 192
#define X384 384
#define NNODES 504   // 256 leaves + 128 + 64 + 32 + 16 + 8
#define NSUB 6       // k stages of 64
#define PGRID 592    // persistent grid: 4 CTAs/SM x 148 SMs (co-resident)

// Scratch (allocation-free rule: __device__ globals)
__device__ __nv_bfloat16 g_Vbf[(size_t)H * X384 * X384];  // 54 MB bf16 V (written by level 0)
__device__ __nv_bfloat16 g_WTbf[256 * X384];              // W^T bf16, rows 192..255 zero
__device__ float g_WTf32[256 * X384];                     // W^T fp32 (level-0 path), padded
__device__ __nv_bfloat16 g_cB[128 * X384];                // current-level node vectors, bf16
__device__ float g_nodes[NNODES * H];
__device__ float g_part[7][H][128];                        // 6 x-block partials + Wx
__device__ unsigned g_bar_ctr;                             // persistent-kernel barrier counter

// ---------------------------------------------------------------------------
// helpers
// ---------------------------------------------------------------------------
__device__ __forceinline__ void cp16(void* smem, const void* gmem) {
    unsigned s = (unsigned)__cvta_generic_to_shared(smem);
    asm volatile("cp.async.cg.shared.global [%0], [%1], 16;\n" :: "r"(s), "l"(gmem));
}
__device__ __forceinline__ void cp_commit() { asm volatile("cp.async.commit_group;\n"); }
template <int N>
__device__ __forceinline__ void cp_wait() { asm volatile("cp.async.wait_group %0;\n" :: "n"(N)); }

__device__ __forceinline__ void ldmx4(unsigned* a, unsigned saddr) {
    asm volatile("ldmatrix.sync.aligned.m8n8.x4.shared.b16 {%0,%1,%2,%3}, [%4];"
                 : "=r"(a[0]), "=r"(a[1]), "=r"(a[2]), "=r"(a[3]) : "r"(saddr));
}
__device__ __forceinline__ void ldmx2(unsigned* a, unsigned saddr) {
    asm volatile("ldmatrix.sync.aligned.m8n8.x2.shared.b16 {%0,%1}, [%2];"
                 : "=r"(a[0]), "=r"(a[1]) : "r"(saddr));
}
__device__ __forceinline__ void mma16816(float* d, const unsigned* a, unsigned b0, unsigned b1) {
    asm volatile(
        "mma.sync.aligned.m16n8k16.row.col.f32.bf16.bf16.f32 "
        "{%0,%1,%2,%3},{%4,%5,%6,%7},{%8,%9},{%0,%1,%2,%3};"
        : "+f"(d[0]), "+f"(d[1]), "+f"(d[2]), "+f"(d[3])
        : "r"(a[0]), "r"(a[1]), "r"(a[2]), "r"(a[3]), "r"(b0), "r"(b1));
}
__device__ __forceinline__ unsigned pack_bf2(float x, float y) {
    __nv_bfloat162 t;
    t.x = __float2bfloat16_rn(x); t.y = __float2bfloat16_rn(y);
    return *(const unsigned*)&t;
}
// L1-bypassing bf16 load (persistent kernel reads across grid barriers)
__device__ __forceinline__ float ldcg_bf16(const __nv_bfloat16* p) {
    unsigned short u;
    asm volatile("ld.global.cg.u16 %0, [%1];" : "=h"(u) : "l"(p));
    __nv_bfloat16 b = *reinterpret_cast<__nv_bfloat16*>(&u);
    return __bfloat162float(b);
}

// ---------------------------------------------------------------------------
// Setup: W^T (fp32 + bf16), leaf gather + level-0 B, barrier counter reset
// grid = 256, block = 192
// ---------------------------------------------------------------------------
__global__ void setup_kernel(const float* __restrict__ W,
                             const float* __restrict__ embed,
                             const int* __restrict__ leaf_ids) {
    int bid = blockIdx.x, t = threadIdx.x;
    if (bid == 0 && t == 0) g_bar_ctr = 0;
    // W^T rows
    int h = bid;
    for (int y = t; y < X384; y += 192) {
        float v = (h < H) ? W[y * H + h] : 0.f;
        g_WTf32[h * X384 + y] = v;
        g_WTbf[h * X384 + y] = __float2bfloat16_rn(v);
    }
    // leaf gather (n = bid < 256)
    int n = bid;
    float v = embed[(size_t)leaf_ids[n] * H + t];
    g_nodes[n * H + t] = v;
    int q = n & 31;
    int m = (n >> 5) * 16 + (q >> 1);
    g_cB[m * X384 + (q & 1) * H + t] = __float2bfloat16_rn(v);
}

// ---------------------------------------------------------------------------
// Level-0 GEMM (CONV): reads V fp32 from Vt, converts in-reg, STS bf16 +
// STG bf16 to g_Vbf; NTILE=128, grid (1156,1). Same as R16.
// ---------------------------------------------------------------------------
__global__ void __launch_bounds__(256, 2)
gemm_level0(const float* __restrict__ Vt) {
    constexpr int NTILE = 128;
    constexpr int NT = NTILE / 16;
    constexpr int NP = NT / 2;
    constexpr int NBCH = NTILE * 8;
    constexpr int BSTG = NTILE * 128;

    extern __shared__ char smraw[];
    char* As = smraw;                            // [2][64][128B]
    char* Bp = smraw + 2 * 8192;                 // [3][NTILE][128B]
    float* ysm = (float*)(Bp + 3 * BSTG);        // [4][NTILE]

    const int mblk = blockIdx.x;
    const bool isW = (mblk >= 1152);
    const int tid = threadIdx.x;

    const float* Agf = isW ? (g_WTf32 + (size_t)(mblk - 1152) * 64 * X384)
                           : (Vt + ((size_t)(mblk / 6) * X384 + (mblk % 6) * 64) * X384);
    __nv_bfloat16* Aout = isW ? nullptr
                              : g_Vbf + ((size_t)(mblk / 6) * X384 + (mblk % 6) * 64) * X384;

    const int crow = tid >> 2, ccf = tid & 3;
    float4 v[4];

    // A prologue (stage 0)
    {
        const float4* src = (const float4*)(Agf + crow * X384 + ccf * 16);
        #pragma unroll
        for (int q = 0; q < 4; q++) v[q] = src[q];
        unsigned pk[8];
        #pragma unroll
        for (int q = 0; q < 4; q++) {
            pk[2 * q]     = pack_bf2(v[q].x, v[q].y);
            pk[2 * q + 1] = pack_bf2(v[q].z, v[q].w);
        }
        uint4 lo = make_uint4(pk[0], pk[1], pk[2], pk[3]);
        uint4 hi = make_uint4(pk[4], pk[5], pk[6], pk[7]);
        char* slotp = As + crow * 128;
        *(uint4*)(slotp + (((2 * ccf)     ^ (crow & 7)) << 4)) = lo;
        *(uint4*)(slotp + (((2 * ccf + 1) ^ (crow & 7)) << 4)) = hi;
        if (!isW) {
            uint4* dst = (uint4*)(Aout + crow * X384 + ccf * 16);
            dst[0] = lo; dst[1] = hi;
        }
    }
    // B prologue: stages 0,1
    #pragma unroll
    for (int s = 0; s < 2; s++) {
        char* Bd = Bp + s * BSTG;
        for (int j = tid; j < NBCH; j += 256) {
            int n = j >> 3, c = j & 7;
            cp16(Bd + n * 128 + (((c ^ (n & 7)) << 4)),
                 g_cB + (size_t)n * X384 + s * 64 + c * 8);
        }
        cp_commit();
    }

    const int warp = tid >> 5, lane = tid & 31;
    const int wm = warp & 3, wn = warp >> 2;
    const int g = lane >> 2, tg = lane & 3;
    const int m0 = wm * 16;
    const int nb0 = wn * (NT * 8);

    const unsigned As_u = (unsigned)__cvta_generic_to_shared(As);
    const unsigned Bs_u = (unsigned)__cvta_generic_to_shared(Bp);

    const int am = m0 + (lane & 15);
    unsigned a_off[4];
    #pragma unroll
    for (int ks = 0; ks < 4; ks++) {
        int c = ks * 2 + (lane >> 4);
        a_off[ks] = (unsigned)(am * 128 + ((c ^ (am & 7)) << 4));
    }
    const int bmm = lane >> 3, brr = lane & 7;
    const int rowo = (bmm & 2) ? 8 : 0, kos = bmm & 1;
    unsigned b_row[NP], b_xm[NP];
    #pragma unroll
    for (int p = 0; p < NP; p++) {
        int nr = nb0 + p * 16 + rowo + brr;
        b_row[p] = (unsigned)(nr * 128);
        b_xm[p] = (unsigned)(nr & 7);
    }

    float acc[NT][4];
    #pragma unroll
    for (int nt = 0; nt < NT; nt++)
        #pragma unroll
        for (int q = 0; q < 4; q++) acc[nt][q] = 0.f;

    for (int s = 0; s < NSUB; s++) {
        if (s == NSUB - 1) cp_wait<0>(); else cp_wait<1>();
        __syncthreads();
        const int sn = s + 2;
        if (sn < NSUB) {
            char* Bd = Bp + (sn % 3) * BSTG;
            for (int j = tid; j < NBCH; j += 256) {
                int n = j >> 3, c = j & 7;
                cp16(Bd + n * 128 + (((c ^ (n & 7)) << 4)),
                     g_cB + (size_t)n * X384 + sn * 64 + c * 8);
            }
            cp_commit();
        }
        if (s + 1 < NSUB) {
            const float4* src = (const float4*)(Agf + crow * X384 + (s + 1) * 64 + ccf * 16);
            #pragma unroll
            for (int q = 0; q < 4; q++) v[q] = src[q];
        }

        const unsigned a_stg = As_u + (s & 1) * 8192;
        const unsigned b_stg = Bs_u + (s % 3) * BSTG;

        #pragma unroll
        for (int ks = 0; ks < 4; ks++) {
            unsigned a[4];
            ldmx4(a, a_stg + a_off[ks]);
            const unsigned c = (unsigned)(ks * 2 + kos);
            #pragma unroll
            for (int p = 0; p < NP; p++) {
                unsigned bb[4];
                ldmx4(bb, b_stg + b_row[p] + ((c ^ b_xm[p]) << 4));
                mma16816(acc[2 * p],     a, bb[0], bb[1]);
                mma16816(acc[2 * p + 1], a, bb[2], bb[3]);
            }
        }

        if (s + 1 < NSUB) {
            unsigned pk[8];
            #pragma unroll
            for (int q = 0; q < 4; q++) {
                pk[2 * q]     = pack_bf2(v[q].x, v[q].y);
                pk[2 * q + 1] = pack_bf2(v[q].z, v[q].w);
            }
            uint4 lo = make_uint4(pk[0], pk[1], pk[2], pk[3]);
            uint4 hi = make_uint4(pk[4], pk[5], pk[6], pk[7]);
            char* slotp = As + ((s + 1) & 1) * 8192 + crow * 128;
            *(uint4*)(slotp + (((2 * ccf)     ^ (crow & 7)) << 4)) = lo;
            *(uint4*)(slotp + (((2 * ccf + 1) ^ (crow & 7)) << 4)) = hi;
            if (!isW) {
                uint4* dst = (uint4*)(Aout + crow * X384 + (s + 1) * 64 + ccf * 16);
                dst[0] = lo; dst[1] = hi;
            }
        }
    }

    if (!isW) {
        const int xb = mblk % 6, hh = mblk / 6;
        const int xf = xb * 64 + m0 + g;
        #pragma unroll
        for (int nt = 0; nt < NT; nt++) {
            int nl = nb0 + nt * 8 + 2 * tg;
            const __nv_bfloat16* c0p = g_cB + (size_t)nl * X384 + xf;
            const __nv_bfloat16* c1p = c0p + X384;
            float p0 = __bfloat162float(c0p[0]) * acc[nt][0]
                     + __bfloat162float(c0p[8]) * acc[nt][2];
            float p1 = __bfloat162float(c1p[0]) * acc[nt][1]
                     + __bfloat162float(c1p[8]) * acc[nt][3];
            #pragma unroll
            for (int sh = 4; sh < 32; sh <<= 1) {
                p0 += __shfl_xor_sync(0xffffffffu, p0, sh);
                p1 += __shfl_xor_sync(0xffffffffu, p1, sh);
            }
            if (g == 0) {
                ysm[wm * NTILE + nl] = p0;
                ysm[wm * NTILE + nl + 1] = p1;
            }
        }
        __syncthreads();
        for (int n = tid; n < NTILE; n += 256) {
            float vv = ysm[n] + ysm[NTILE + n] + ysm[2 * NTILE + n] + ysm[3 * NTILE + n];
            g_part[xb][hh][n] = vv;
        }
    } else {
        const int hb = (mblk - 1152) * 64;
        int hh = hb + m0 + g;
        #pragma unroll
        for (int nt = 0; nt < NT; nt++) {
            int n = nb0 + nt * 8 + 2 * tg;
            if (hh < H) {
                g_part[6][hh][n]     = acc[nt][0];
                g_part[6][hh][n + 1] = acc[nt][1];
            }
            if (hh + 8 < H) {
                g_part[6][hh + 8][n]     = acc[nt][2];
                g_part[6][hh + 8][n + 1] = acc[nt][3];
            }
        }
    }
}

// ---------------------------------------------------------------------------
// Persistent kernel device bodies
// ---------------------------------------------------------------------------
__device__ __forceinline__ void grid_bar(unsigned target) {
    __syncthreads();
    if (threadIdx.x == 0) {
        __threadfence();
        atomicAdd(&g_bar_ctr, 1u);
        while (*(volatile unsigned*)&g_bar_ctr < target) __nanosleep(32);
        __threadfence();
    }
    __syncthreads();
}

// gemm body for one m-block (n0 = 0). A from g_Vbf/g_WTbf, B ring from g_cB.
template <int NTILE>
__device__ __forceinline__ void gemm_body(int mblk, char* smraw) {
    constexpr int NT = NTILE / 16;
    constexpr int NP = NT / 2;
    constexpr int NBCH = NTILE * 8;
    constexpr int BSTG = NTILE * 128;

    char* As = smraw;                            // [3][64][128B]
    char* Bp = smraw + 3 * 8192;                 // [3][NTILE][128B]
    float* ysm = (float*)(Bp + 3 * BSTG);        // [4][NTILE]

    const bool isW = (mblk >= 1152);
    const __nv_bfloat16* Ag = isW
        ? (g_WTbf + (size_t)(mblk - 1152) * 64 * X384)
        : (g_Vbf + ((size_t)(mblk / 6) * X384 + (mblk % 6) * 64) * X384);

    const int tid = threadIdx.x;
    const int ar = tid >> 3, ac = tid & 7;

    #pragma unroll
    for (int s = 0; s < 2; s++) {
        char* Ad = As + s * 8192;
        #pragma unroll
        for (int t = 0; t < 2; t++) {
            int r = ar + t * 32;
            cp16(Ad + r * 128 + (((ac ^ (r & 7)) << 4)), Ag + r * X384 + s * 64 + ac * 8);
        }
        char* Bd = Bp + s * BSTG;
        for (int j = tid; j < NBCH; j += 256) {
            int n = j >> 3, c = j & 7;
            cp16(Bd + n * 128 + (((c ^ (n & 7)) << 4)),
                 g_cB + (size_t)n * X384 + s * 64 + c * 8);
        }
        cp_commit();
    }

    const int warp = tid >> 5, lane = tid & 31;
    const int wm = warp & 3, wn = warp >> 2;
    const int g = lane >> 2, tg = lane & 3;
    const int m0 = wm * 16;
    const int nb0 = wn * (NT * 8);

    const unsigned As_u = (unsigned)__cvta_generic_to_shared(As);
    const unsigned Bs_u = (unsigned)__cvta_generic_to_shared(Bp);

    const int am = m0 + (lane & 15);
    unsigned a_off[4];
    #pragma unroll
    for (int ks = 0; ks < 4; ks++) {
        int c = ks * 2 + (lane >> 4);
        a_off[ks] = (unsigned)(am * 128 + ((c ^ (am & 7)) << 4));
    }
    const int bmm = lane >> 3, brr = lane & 7;
    const int rowo = (bmm & 2) ? 8 : 0, kos = bmm & 1;
    unsigned b_row[NP > 0 ? NP : 1], b_xm[NP > 0 ? NP : 1];
    #pragma unroll
    for (int p = 0; p < (NP > 0 ? NP : 1); p++) {
        int nr = nb0 + p * 16 + rowo + brr;
        b_row[p] = (unsigned)(nr * 128);
        b_xm[p] = (unsigned)(nr & 7);
    }
    const int nr1 = nb0 + brr;
    const unsigned b_row1 = (unsigned)(nr1 * 128), b_xm1 = (unsigned)(nr1 & 7);

    float acc[NT][4];
    #pragma unroll
    for (int nt = 0; nt < NT; nt++)
        #pragma unroll
        for (int q = 0; q < 4; q++) acc[nt][q] = 0.f;

    for (int s = 0; s < NSUB; s++) {
        if (s == NSUB - 1) cp_wait<0>(); else cp_wait<1>();
        __syncthreads();
        const int sn = s + 2;
        if (sn < NSUB) {
            char* Ad = As + (sn % 3) * 8192;
            #pragma unroll
            for (int t = 0; t < 2; t++) {
                int r = ar + t * 32;
                cp16(Ad + r * 128 + (((ac ^ (r & 7)) << 4)), Ag + r * X384 + sn * 64 + ac * 8);
            }
            char* Bd = Bp + (sn % 3) * BSTG;
            for (int j = tid; j < NBCH; j += 256) {
                int n = j >> 3, c = j & 7;
                cp16(Bd + n * 128 + (((c ^ (n & 7)) << 4)),
                     g_cB + (size_t)n * X384 + sn * 64 + c * 8);
            }
            cp_commit();
        }

        const unsigned a_stg = As_u + (s % 3) * 8192;
        const unsigned b_stg = Bs_u + (s % 3) * BSTG;

        #pragma unroll
        for (int ks = 0; ks < 4; ks++) {
            unsigned a[4];
            ldmx4(a, a_stg + a_off[ks]);
            const unsigned c = (unsigned)(ks * 2 + kos);
            if constexpr (NP > 0) {
                #pragma unroll
                for (int p = 0; p < NP; p++) {
                    unsigned bb[4];
                    ldmx4(bb, b_stg + b_row[p] + ((c ^ b_xm[p]) << 4));
                    mma16816(acc[2 * p],     a, bb[0], bb[1]);
                    mma16816(acc[2 * p + 1], a, bb[2], bb[3]);
                }
            } else {
                unsigned bb[2];
                ldmx2(bb, b_stg + b_row1 + ((c ^ b_xm1) << 4));
                mma16816(acc[0], a, bb[0], bb[1]);
            }
        }
    }

    if (!isW) {
        const int xb = mblk % 6, hh = mblk / 6;
        const int xf = xb * 64 + m0 + g;
        #pragma unroll
        for (int nt = 0; nt < NT; nt++) {
            int nl = nb0 + nt * 8 + 2 * tg;
            const __nv_bfloat16* c0p = g_cB + (size_t)nl * X384 + xf;
            const __nv_bfloat16* c1p = c0p + X384;
            float p0 = ldcg_bf16(c0p)     * acc[nt][0] + ldcg_bf16(c0p + 8) * acc[nt][2];
            float p1 = ldcg_bf16(c1p)     * acc[nt][1] + ldcg_bf16(c1p + 8) * acc[nt][3];
            #pragma unroll
            for (int sh = 4; sh < 32; sh <<= 1) {
                p0 += __shfl_xor_sync(0xffffffffu, p0, sh);
                p1 += __shfl_xor_sync(0xffffffffu, p1, sh);
            }
            if (g == 0) {
                ysm[wm * NTILE + nl] = p0;
                ysm[wm * NTILE + nl + 1] = p1;
            }
        }
        __syncthreads();
        for (int n = tid; n < NTILE; n += 256) {
            float vv = ysm[n] + ysm[NTILE + n] + ysm[2 * NTILE + n] + ysm[3 * NTILE + n];
            g_part[xb][hh][n] = vv;
        }
        __syncthreads();   // ysm reuse safety across m-block iterations
    } else {
        const int hb = (mblk - 1152) * 64;
        int hh = hb + m0 + g;
        #pragma unroll
        for (int nt = 0; nt < NT; nt++) {
            int n = nb0 + nt * 8 + 2 * tg;
            if (hh < H) {
                g_part[6][hh][n]     = acc[nt][0];
                g_part[6][hh][n + 1] = acc[nt][1];
            }
            if (hh + 8 < H) {
                g_part[6][hh + 8][n]     = acc[nt][2];
                g_part[6][hh + 8][n + 1] = acc[nt][3];
            }
        }
    }
}

__device__ __forceinline__ void finalize_body(int outBase, int Nout, int hasNext,
                                              const float* __restrict__ bias) {
    int n = blockIdx.x, t = threadIdx.x;
    if (n < Nout && t < H) {
        float v = bias[t];
        #pragma unroll
        for (int i = 0; i < 7; i++) v += __ldcg(&g_part[i][t][n]);
        v = tanhf(v);
        g_nodes[(size_t)(outBase + n) * H + t] = v;
        if (hasNext) {
            int npt = Nout >> 3;
            int bt = n / npt, j = n - bt * npt;
            int m = bt * (npt >> 1) + (j >> 1);
            g_cB[m * X384 + (j & 1) * H + t] = __float2bfloat16_rn(v);
        }
    }
}

__device__ __forceinline__ void logits_body(const float* __restrict__ Wout_w,
                                            const float* __restrict__ Wout_b,
                                            float* __restrict__ out) {
    int node = blockIdx.x;
    if (node >= NNODES || threadIdx.x >= 32) return;
    int lane = threadIdx.x;
    const float* v = g_nodes + (size_t)node * H;
    float l[5];
    #pragma unroll
    for (int o = 0; o < 5; o++) {
        float p = 0.f;
        #pragma unroll
        for (int i = 0; i < 6; i++) {
            int idx = lane + 32 * i;
            p += v[idx] * Wout_w[o * H + idx];
        }
        #pragma unroll
        for (int s = 16; s; s >>= 1) p += __shfl_xor_sync(0xffffffffu, p, s);
        l[o] = p + Wout_b[o];
    }
    if (lane == 0) {
        float m = l[0];
        #pragma unroll
        for (int o = 1; o < 5; o++) m = fmaxf(m, l[o]);
        float s = 0.f;
        #pragma unroll
        for (int o = 0; o < 5; o++) s += expf(l[o] - m);
        float ls = logf(s);
        #pragma unroll
        for (int o = 0; o < 5; o++) out[node * 5 + o] = l[o] - m - ls;
    }
}

// ---------------------------------------------------------------------------
// Persistent kernel: finalize0 | levels 1-4 (gemm + finalize) | logits
// grid = PGRID (co-resident), 256 threads, smem = level-1 size (largest)
// ---------------------------------------------------------------------------
__global__ void __launch_bounds__(256, 4)
persistent_kernel(const float* __restrict__ bias,
                  const float* __restrict__ Wout_w,
                  const float* __restrict__ Wout_b,
                  float* __restrict__ out) {
    extern __shared__ char smraw[];
    unsigned phase = 0;
    const unsigned G = gridDim.x;

    // phase: finalize level 0 (g_part from gemm_level0 launch)
    finalize_body(256, 128, 1, bias);
    grid_bar(++phase * G);

    // level 1: 128 -> 64 (NTILE=64)
    for (int m = blockIdx.x; m < 1156; m += G) gemm_body<64>(m, smraw);
    grid_bar(++phase * G);
    finalize_body(384, 64, 1, bias);
    grid_bar(++phase * G);

    // level 2: 64 -> 32 (NTILE=32)
    for (int m = blockIdx.x; m < 1156; m += G) gemm_body<32>(m, smraw);
    grid_bar(++phase * G);
    finalize_body(448, 32, 1, bias);
    grid_bar(++phase * G);

    // level 3: 32 -> 16 (NTILE=16)
    for (int m = blockIdx.x; m < 1156; m += G) gemm_body<16>(m, smraw);
    grid_bar(++phase * G);
    finalize_body(480, 16, 1, bias);
    grid_bar(++phase * G);

    // level 4: 16 -> 8 (NTILE=16; B rows 8..15 stale -> unused columns)
    for (int m = blockIdx.x; m < 1156; m += G) gemm_body<16>(m, smraw);
    grid_bar(++phase * G);
    finalize_body(496, 8, 0, bias);
    grid_bar(++phase * G);

    logits_body(Wout_w, Wout_b, out);
}

// ---------------------------------------------------------------------------
extern "C" void kernel_launch(void* const* d_in, const int* in_sizes, int n_in,
                              void* d_out, int out_size) {
    const float* embed  = (const float*)d_in[0];
    const float* Vt     = (const float*)d_in[1];
    const float* W      = (const float*)d_in[2];
    const float* b      = (const float*)d_in[3];
    const float* Wout_w = (const float*)d_in[4];
    const float* Wout_b = (const float*)d_in[5];
    const int*   leaf   = (const int*)d_in[6];
    float* out = (float*)d_out;

    const int smem0 = 2 * 8192 + 3 * 128 * 128 + 4 * 128 * 4;          // 67584
    const int smemP = 3 * 8192 + 3 * 64 * 128 + 4 * 64 * 4;            // 50176

    static bool attr_set = false;
    if (!attr_set) {
        cudaFuncSetAttribute(gemm_level0, cudaFuncAttributeMaxDynamicSharedMemorySize, smem0);
        cudaFuncSetAttribute(persistent_kernel, cudaFuncAttributeMaxDynamicSharedMemorySize, smemP);
        attr_set = true;
    }

    setup_kernel<<<256, 192>>>(W, embed, leaf);               // WT + leaves + bar reset
    gemm_level0<<<dim3(1156, 1), 256, smem0>>>(Vt);           // level 0 + V convert
    persistent_kernel<<<PGRID, 256, smemP>>>(b, Wout_w, Wout_b, out);
}